// round 12
// baseline (speedup 1.0000x reference)
#include <cuda_runtime.h>
#include <cstdint>

typedef unsigned long long ull;

// Problem constants (fixed by the dataset)
#define RWIN   3
#define NW     49          // (2R+1)^2
#define NSIDE  128
#define NN     (NSIDE*NSIDE)
#define KCH    131
#define CCH    21
#define BB     2

// Scratch (device globals; no allocation allowed)
// (t,u) = (exp(xm), exp(-xm)) pairs; float4 = 2 pairs, 16B-aligned IO.
__device__ float4 g_TU[(size_t)BB * KCH * NN / 2];
// g_A[w][b][pix] : per-window-tap mixing weights (49 planes, coalesced)
__device__ float  g_A[(size_t)NW * BB * NN];

// ---------------------------------------------------------------------------
// Kernel P: precompute (exp(xm), exp(-xm)). 2 float4 per thread (MLP=4).
// ---------------------------------------------------------------------------
__global__ __launch_bounds__(256) void k_pre(const float4* __restrict__ x,
                                             const int4* __restrict__ mask) {
    const int total4 = BB * KCH * NN / 4;
    int i0 = blockIdx.x * 512 + threadIdx.x;
    int i1 = i0 + 256;
    bool ok0 = i0 < total4, ok1 = i1 < total4;
    float4 v0, v1; int4 m0, m1;
    if (ok0) { v0 = x[i0]; m0 = mask[(i0 / (KCH * NN / 4)) * (NN / 4) + (i0 & (NN / 4 - 1))]; }
    if (ok1) { v1 = x[i1]; m1 = mask[(i1 / (KCH * NN / 4)) * (NN / 4) + (i1 & (NN / 4 - 1))]; }
    if (ok0) {
        float a = m0.x ? v0.x : 0.f, b = m0.y ? v0.y : 0.f;
        float c = m0.z ? v0.z : 0.f, d = m0.w ? v0.w : 0.f;
        g_TU[2 * (size_t)i0]     = make_float4(__expf(a), __expf(-a), __expf(b), __expf(-b));
        g_TU[2 * (size_t)i0 + 1] = make_float4(__expf(c), __expf(-c), __expf(d), __expf(-d));
    }
    if (ok1) {
        float a = m1.x ? v1.x : 0.f, b = m1.y ? v1.y : 0.f;
        float c = m1.z ? v1.z : 0.f, d = m1.w ? v1.w : 0.f;
        g_TU[2 * (size_t)i1]     = make_float4(__expf(a), __expf(-a), __expf(b), __expf(-b));
        g_TU[2 * (size_t)i1 + 1] = make_float4(__expf(c), __expf(-c), __expf(d), __expf(-d));
    }
}

// ---------------------------------------------------------------------------
// Kernel W: per-pixel window weights A[w].
//   e_w = max(u_c*t_b, t_c*u_b) = exp(|xm_c - xm_b|)   (0 for OOB since TU=0)
//   A[w] = sum_k conv[k] * e_w / sum_w e_w   (mask applied at writeout)
//
// 8x8 pixel tile, 128 threads = 32 groups of (2 adjacent px) x 4 row-threads:
//   q=0 -> dy{0,1}, q=1 -> dy{2,3}, q=2 -> dy{4,5}, q=3 -> dy{6}
// Taps for both px of a group come from 4 aligned LDS.128 (8 pairs, all used:
// px0 -> p[0..6], px1 -> p[1..7]). S reduced over the 4 q-lanes via shfl_xor.
// 3-deep cp.async pipeline, one __syncthreads per k.
// ---------------------------------------------------------------------------
#define TI  8
#define TJ  8
#define HWD 14      // halo tile = (TI+6) x (TJ+6)
#define STW 26      // smem row stride in 8-byte words (even -> 16B alignment)

__device__ __forceinline__ float emax(ull Cw, ull p) {
    ull mr;
    asm("mul.rn.f32x2 %0, %1, %2;" : "=l"(mr) : "l"(Cw), "l"(p));
    unsigned ra, rb;
    asm("mov.b64 {%0,%1}, %2;" : "=r"(ra), "=r"(rb) : "l"(mr));
    return fmaxf(__uint_as_float(ra), __uint_as_float(rb));
}

__global__ __launch_bounds__(128, 4) void k_weights(const int* __restrict__ mask,
                                                    const float* __restrict__ conv) {
    __shared__ __align__(16) ull tu[3][HWD * STW];   // 3 x 2912 B

    const int tid = threadIdx.x;
    const int b   = blockIdx.z;
    const int ti0 = blockIdx.y * TI, tj0 = blockIdx.x * TJ;
    const int g   = tid >> 2, q = tid & 3;       // group, row-quarter
    const int pi  = g >> 2, gj = g & 3;          // 8 tile rows x 4 col-groups
    const int pj0 = 2 * gj;
    const int gi  = ti0 + pi;
    const int pix0 = gi * NSIDE + tj0 + pj0;
    const int msk0 = mask[b * NN + pix0];
    const int msk1 = mask[b * NN + pix0 + 1];
    const bool q3  = (q == 3);

    // --- async 14x14 float2 tile loader, zero-fill out of bounds ---
    auto load_tile = [&](int k, int buf) {
        const float2* gsrc = (const float2*)g_TU + (size_t)(b * KCH + k) * NN;
        unsigned sdst = (unsigned)__cvta_generic_to_shared(&tu[buf][0]);
#pragma unroll
        for (int e0 = 0; e0 < 2; e0++) {
            int e = tid + e0 * 128;
            if (e < HWD * HWD) {
                int r = e / HWD, c = e - r * HWD;
                int gi2 = ti0 - 3 + r, gj2 = tj0 - 3 + c;
                bool ok = ((unsigned)gi2 < NSIDE) && ((unsigned)gj2 < NSIDE);
                int gic = min(max(gi2, 0), NSIDE - 1);
                int gjc = min(max(gj2, 0), NSIDE - 1);
                const void* src = (const void*)(gsrc + gic * NSIDE + gjc);
                unsigned dst = sdst + (unsigned)((r * STW + c) * 8);
                int sz = ok ? 8 : 0;   // src-size 0 -> zero fill (kills OOB taps)
                asm volatile("cp.async.ca.shared.global [%0], [%1], 8, %2;\n"
                             :: "r"(dst), "l"(src), "r"(sz));
            }
        }
        asm volatile("cp.async.commit_group;\n");
    };

    float acc0[14], acc1[14];
#pragma unroll
    for (int t = 0; t < 14; t++) { acc0[t] = 0.0f; acc1[t] = 0.0f; }

    load_tile(0, 0);
    load_tile(1, 1);

    for (int k = 0; k < KCH; k++) {
        asm volatile("cp.async.wait_group 1;\n");
        __syncthreads();
        if (k + 2 < KCH) load_tile(k + 2, (k + 2) % 3);

        const ull* T = tu[k % 3];
        // centers for the two pixels: (t,u) -> swapped (u,t)
        ull c0 = T[(pi + 3) * STW + pj0 + 3];
        ull c1 = T[(pi + 3) * STW + pj0 + 4];
        unsigned lo, hi;
        ull Cw0, Cw1;
        asm("mov.b64 {%0,%1}, %2;" : "=r"(lo), "=r"(hi) : "l"(c0));
        asm("mov.b64 %0, {%1,%2};" : "=l"(Cw0) : "r"(hi), "r"(lo));
        asm("mov.b64 {%0,%1}, %2;" : "=r"(lo), "=r"(hi) : "l"(c1));
        asm("mov.b64 %0, {%1,%2};" : "=l"(Cw1) : "r"(hi), "r"(lo));

        float e0[14], e1[14];
        float s0 = 0.0f, s1 = 0.0f;
#pragma unroll
        for (int rr = 0; rr < 2; rr++) {
            if (rr == 0 || !q3) {
                const int row = pi + 2 * q + rr;
                const ulonglong2* rp = (const ulonglong2*)&T[row * STW + pj0];
                ulonglong2 w0 = rp[0], w1 = rp[1], w2 = rp[2], w3 = rp[3];
                ull p[8] = {w0.x, w0.y, w1.x, w1.y, w2.x, w2.y, w3.x, w3.y};
#pragma unroll
                for (int dx = 0; dx < 7; dx++) {
                    float ev0 = emax(Cw0, p[dx]);
                    float ev1 = emax(Cw1, p[dx + 1]);
                    e0[rr * 7 + dx] = ev0;  s0 += ev0;
                    e1[rr * 7 + dx] = ev1;  s1 += ev1;
                }
            }
        }
        // reduce S over the 4 row-threads of this group (lanes 4g..4g+3)
        s0 += __shfl_xor_sync(0xffffffffu, s0, 1);
        s0 += __shfl_xor_sync(0xffffffffu, s0, 2);
        s1 += __shfl_xor_sync(0xffffffffu, s1, 1);
        s1 += __shfl_xor_sync(0xffffffffu, s1, 2);

        float cv  = __ldg(conv + k);
        float co0 = __fdividef(cv, s0);
        float co1 = __fdividef(cv, s1);
#pragma unroll
        for (int t = 0; t < 14; t++) {
            if (t < 7 || !q3) {
                acc0[t] = fmaf(co0, e0[t], acc0[t]);
                acc1[t] = fmaf(co1, e1[t], acc1[t]);
            }
        }
    }

    // writeout: thread owns rows dy = 2q (+1 if q<3); w = dy*7 + dx
#pragma unroll
    for (int rr = 0; rr < 2; rr++) {
        if (rr == 0 || !q3) {
            const int dy = 2 * q + rr;
#pragma unroll
            for (int dx = 0; dx < 7; dx++) {
                const int w = dy * 7 + dx;
                const size_t base = ((size_t)w * BB + b) * NN;
                g_A[base + pix0]     = msk0 ? acc0[rr * 7 + dx] : 0.0f;
                g_A[base + pix0 + 1] = msk1 ? acc1[rr * 7 + dx] : 0.0f;
            }
        }
    }
}

// ---------------------------------------------------------------------------
// Kernel G: output gather, 2 adjacent output pixels per thread.
//   y[b,q,c] = sum_{du,dv} A[w=(3-du)*7+(3-dv)][p=q+(du,dv)] * x2[b,c,p]
// The two outputs (j2, j2+1) share 7/8 of each x2 window row.
// ---------------------------------------------------------------------------
__global__ __launch_bounds__(256) void k_gather(const float* __restrict__ x2,
                                                float* __restrict__ out) {
    const int b   = blockIdx.z;
    const int tid = threadIdx.x;
    const int i2  = blockIdx.y * 16 + (tid >> 4);
    const int j2  = (blockIdx.x * 16 + (tid & 15)) * 2;

    float acc0[CCH], acc1[CCH];
#pragma unroll
    for (int c = 0; c < CCH; c++) { acc0[c] = 0.0f; acc1[c] = 0.0f; }

    const float* x2b = x2 + (size_t)b * CCH * NN;

#pragma unroll 1
    for (int du = -3; du <= 3; du++) {
        const int pi = i2 + du;
        if ((unsigned)pi >= NSIDE) continue;
        const int rowoff = pi * NSIDE;
        // A weights for the 8 columns jc = j2-3+cc (px0 uses cc 0..6, px1 cc 1..7)
        float A0[7], A1[7];
        bool  vld[8];
        int   pcol[8];
#pragma unroll
        for (int cc = 0; cc < 8; cc++) {
            int jc = j2 - 3 + cc;
            vld[cc]  = ((unsigned)jc < NSIDE);
            pcol[cc] = rowoff + min(max(jc, 0), NSIDE - 1);
        }
        const int wrow = (3 - du) * 7;
#pragma unroll
        for (int cc = 0; cc < 7; cc++) {
            const int w0 = wrow + (6 - cc);          // dv0 = cc-3
            A0[cc] = vld[cc] ? g_A[((size_t)w0 * BB + b) * NN + pcol[cc]] : 0.0f;
            const int w1 = wrow + (7 - (cc + 1));    // dv1 = cc-3 for px1 at cc+1
            A1[cc] = vld[cc + 1] ? g_A[((size_t)w1 * BB + b) * NN + pcol[cc + 1]] : 0.0f;
        }
#pragma unroll 1
        for (int c = 0; c < CCH; c++) {
            const float* f = x2b + (size_t)c * NN;
            float fv[8];
#pragma unroll
            for (int cc = 0; cc < 8; cc++)
                fv[cc] = vld[cc] ? f[pcol[cc]] : 0.0f;
#pragma unroll
            for (int cc = 0; cc < 7; cc++) {
                acc0[c] = fmaf(A0[cc], fv[cc], acc0[c]);
                acc1[c] = fmaf(A1[cc], fv[cc + 1], acc1[c]);
            }
        }
    }

    float* o = out + ((size_t)b * NN + i2 * NSIDE + j2) * CCH;
#pragma unroll
    for (int c = 0; c < CCH; c++) { o[c] = acc0[c]; o[CCH + c] = acc1[c]; }
}

// ---------------------------------------------------------------------------
// Launch
// ---------------------------------------------------------------------------
extern "C" void kernel_launch(void* const* d_in, const int* in_sizes, int n_in,
                              void* d_out, int out_size) {
    (void)in_sizes; (void)n_in; (void)out_size;
    const float* integ = (const float*)d_in[0];   // [B,K,N,N] f32
    const float* x2    = (const float*)d_in[1];   // [B,C,N*N] f32
    const int*   mask  = (const int*)d_in[2];     // [B,N,N]   i32
    const float* conv  = (const float*)d_in[3];   // [K]       f32
    float* out = (float*)d_out;                   // [B,N*N,C] f32

    const int total4 = BB * KCH * NN / 4;
    k_pre<<<(total4 + 511) / 512, 256>>>((const float4*)integ, (const int4*)mask);

    dim3 gw(NSIDE / TJ, NSIDE / TI, BB);          // 16 x 16 x 2 = 512 blocks
    k_weights<<<gw, 128>>>(mask, conv);

    dim3 gg(NSIDE / 32, NSIDE / 16, BB);          // 4 x 8 x 2 (2 px / thread)
    k_gather<<<gg, 256>>>(x2, out);
}

// round 14
// speedup vs baseline: 1.2048x; 1.2048x over previous
#include <cuda_runtime.h>
#include <cstdint>

typedef unsigned long long ull;

// Problem constants (fixed by the dataset)
#define RWIN   3
#define NW     49          // (2R+1)^2
#define NSIDE  128
#define NN     (NSIDE*NSIDE)
#define KCH    131
#define CCH    21
#define BB     2

// Scratch (device globals; no allocation allowed)
// (t,u) = (exp(xm), exp(-xm)) pairs; float4 = 2 pairs, 16B-aligned IO.
__device__ float4 g_TU[(size_t)BB * KCH * NN / 2];
// g_A[w][b][pix] : per-window-tap mixing weights (49 planes, coalesced)
__device__ float  g_A[(size_t)NW * BB * NN];

// ---------------------------------------------------------------------------
// Kernel P: precompute (exp(xm), exp(-xm)). 4 float4 per thread (MLP=8).
// total4 = 1,073,152 = 1048 * 1024 exactly -> no bounds checks.
// ---------------------------------------------------------------------------
__global__ __launch_bounds__(256) void k_pre(const float4* __restrict__ x,
                                             const int4* __restrict__ mask) {
    const int base = blockIdx.x * 1024 + threadIdx.x;
    int idx[4];
    float4 v[4];
    int4 m[4];
#pragma unroll
    for (int j = 0; j < 4; j++) { idx[j] = base + 256 * j; v[j] = x[idx[j]]; }
#pragma unroll
    for (int j = 0; j < 4; j++) {
        int b = idx[j] / (KCH * NN / 4);
        int pix4 = idx[j] & (NN / 4 - 1);
        m[j] = mask[b * (NN / 4) + pix4];
    }
#pragma unroll
    for (int j = 0; j < 4; j++) {
        float a = m[j].x ? v[j].x : 0.f, bb = m[j].y ? v[j].y : 0.f;
        float c = m[j].z ? v[j].z : 0.f, d  = m[j].w ? v[j].w : 0.f;
        g_TU[2 * (size_t)idx[j]]     = make_float4(__expf(a), __expf(-a), __expf(bb), __expf(-bb));
        g_TU[2 * (size_t)idx[j] + 1] = make_float4(__expf(c), __expf(-c), __expf(d),  __expf(-d));
    }
}

// ---------------------------------------------------------------------------
// Kernel W: per-pixel window weights A[w].
//   e_w = max(u_c*t_b, t_c*u_b) = exp(|xm_c - xm_b|)   (0 for OOB since TU=0)
//   A[w] = sum_k conv[k] * e_w / sum_w e_w              (selected pixels only)
//
// 8x8 pixel tile, 128 threads = 2 threads/pixel split by window ROW:
//   half0 -> dy in [0,3] (28 taps), half1 -> dy in [4,6] (21 taps).
// TWO channels per pipeline stage (66 stages instead of 131) -> half the
// barriers, two independent dep-chains per stage. Tree-style S reduction.
// ---------------------------------------------------------------------------
#define TI  8
#define TJ  8
#define HWD 14      // halo tile = (TI+6) x (TJ+6)
#define STW 26      // smem row stride in 8-byte words

#define NPAIR ((KCH + 1) / 2)   // 66

__global__ __launch_bounds__(128, 3) void k_weights(const int* __restrict__ mask,
                                                    const float* __restrict__ conv) {
    __shared__ __align__(16) ull tu[3][2][HWD * STW];   // 3 stages x 2 channels

    const int tid  = threadIdx.x;
    const int b    = blockIdx.z;
    const int ti0  = blockIdx.y * TI, tj0 = blockIdx.x * TJ;
    const int px   = tid >> 1, half = tid & 1;
    const int pi   = px >> 3, pj = px & 7;
    const int pix  = (ti0 + pi) * NSIDE + tj0 + pj;
    const int msk  = mask[b * NN + pix];
    const int base = (pi + 4 * half) * STW + pj;     // first tap row for my dy range
    const int cbase = (pi + 3) * STW + (pj + 3);     // center (dy=3,dx=3)

    // --- one channel's 14x14 float2 tile via cp.async (no commit) ---
    auto load_ch = [&](int k, ull* dsts) {
        const float2* gsrc = (const float2*)g_TU + (size_t)(b * KCH + k) * NN;
        unsigned sdst = (unsigned)__cvta_generic_to_shared(dsts);
#pragma unroll
        for (int e0 = 0; e0 < 2; e0++) {
            int e = tid + e0 * 128;
            if (e < HWD * HWD) {
                int r = e / HWD, c = e - r * HWD;
                int gi2 = ti0 - 3 + r, gj2 = tj0 - 3 + c;
                bool ok = ((unsigned)gi2 < NSIDE) && ((unsigned)gj2 < NSIDE);
                int gic = min(max(gi2, 0), NSIDE - 1);
                int gjc = min(max(gj2, 0), NSIDE - 1);
                const void* src = (const void*)(gsrc + gic * NSIDE + gjc);
                unsigned dst = sdst + (unsigned)((r * STW + c) * 8);
                int sz = ok ? 8 : 0;   // src-size 0 -> zero fill (kills OOB taps)
                asm volatile("cp.async.ca.shared.global [%0], [%1], 8, %2;\n"
                             :: "r"(dst), "l"(src), "r"(sz));
            }
        }
    };
    auto load_pair = [&](int kp, int buf) {
        int k0 = 2 * kp;
        load_ch(k0, tu[buf][0]);
        if (k0 + 1 < KCH) load_ch(k0 + 1, tu[buf][1]);
        asm volatile("cp.async.commit_group;\n");
    };

    float acc[28];
#pragma unroll
    for (int t = 0; t < 28; t++) acc[t] = 0.0f;

    // --- per-channel compute (R9-proven math; tree-style S) ---
    auto compute = [&](const ull* __restrict__ T, float cv) {
        ull c64 = T[cbase];                       // (t_c, u_c)
        unsigned clo, chi;
        asm("mov.b64 {%0,%1}, %2;" : "=r"(clo), "=r"(chi) : "l"(c64));
        ull Cw;                                   // (u_c, t_c)
        asm("mov.b64 %0, {%1,%2};" : "=l"(Cw) : "r"(chi), "r"(clo));

        float e[28];
        float s0 = 0.f, s1 = 0.f, s2 = 0.f, s3 = 0.f;
#pragma unroll
        for (int r = 0; r < 4; r++) {
            if (r < 3 || half == 0) {             // half1 has only 3 rows
#pragma unroll
                for (int dx = 0; dx < 7; dx++) {
                    ull p = T[base + r * STW + dx];     // (t_b, u_b)
                    ull mr;
                    asm("mul.rn.f32x2 %0, %1, %2;" : "=l"(mr) : "l"(Cw), "l"(p));
                    unsigned ra, rb;
                    asm("mov.b64 {%0,%1}, %2;" : "=r"(ra), "=r"(rb) : "l"(mr));
                    float ev = fmaxf(__uint_as_float(ra), __uint_as_float(rb));
                    const int t = r * 7 + dx;
                    e[t] = ev;
                    if      ((t & 3) == 0) s0 += ev;
                    else if ((t & 3) == 1) s1 += ev;
                    else if ((t & 3) == 2) s2 += ev;
                    else                   s3 += ev;
                }
            }
        }
        float s = (s0 + s1) + (s2 + s3);
        // pair lanes (2p, 2p+1) share the pixel -> same msk -> both present
        float stot = s + __shfl_xor_sync(__activemask(), s, 1);
        float coeff = __fdividef(cv, stot);
#pragma unroll
        for (int t = 0; t < 28; t++)
            if (t < 28 - 7 * half)
                acc[t] = fmaf(coeff, e[t], acc[t]);
    };

    load_pair(0, 0);
    load_pair(1, 1);

    for (int kp = 0; kp < NPAIR; kp++) {
        asm volatile("cp.async.wait_group 1;\n");
        __syncthreads();
        if (kp + 2 < NPAIR) load_pair(kp + 2, (kp + 2) % 3);

        if (msk) {
            const int k0 = 2 * kp;
            float cv0 = __ldg(conv + k0);
            compute(tu[kp % 3][0], cv0);
            if (k0 + 1 < KCH) {
                float cv1 = __ldg(conv + k0 + 1);
                compute(tu[kp % 3][1], cv1);
            }
        }
        __syncthreads();        // protect stage buffer reuse across warps
    }

    // writeout: half0 -> w 0..27, half1 -> w 28..48; unselected rows = 0
    const int wb = half ? 28 : 0;
#pragma unroll
    for (int t = 0; t < 28; t++)
        if (t < 28 - 7 * half)
            g_A[((size_t)(wb + t) * BB + b) * NN + pix] = msk ? acc[t] : 0.0f;
}

// ---------------------------------------------------------------------------
// Kernel G: output gather (R9 known-good, 1 px/thread).
//   y[b, q=(i,j), c] = sum_{du,dv in [-3,3]} A[w=(3-du)*7+(3-dv)][p=(i+du,j+dv)]
//                      * x2[b, c, p]
// ---------------------------------------------------------------------------
__global__ __launch_bounds__(256) void k_gather(const float* __restrict__ x2,
                                                float* __restrict__ out) {
    const int b  = blockIdx.z;
    const int tid = threadIdx.x;
    const int i2 = blockIdx.y * 16 + (tid >> 4);
    const int j2 = blockIdx.x * 16 + (tid & 15);

    float acc[CCH];
#pragma unroll
    for (int c = 0; c < CCH; c++) acc[c] = 0.0f;

    const float* x2b = x2 + (size_t)b * CCH * NN;

#pragma unroll 1
    for (int du = -3; du <= 3; du++) {
        const int pi = i2 + du;
        if ((unsigned)pi >= NSIDE) continue;
#pragma unroll 1
        for (int dv = -3; dv <= 3; dv++) {
            const int pj = j2 + dv;
            if ((unsigned)pj >= NSIDE) continue;
            const int w = (3 - du) * 7 + (3 - dv);
            const int p = pi * NSIDE + pj;
            const float a = g_A[((size_t)w * BB + b) * NN + p];
            const float* f = x2b + p;
#pragma unroll
            for (int c = 0; c < CCH; c++)
                acc[c] = fmaf(a, f[(size_t)c * NN], acc[c]);
        }
    }

    float* o = out + ((size_t)b * NN + i2 * NSIDE + j2) * CCH;
#pragma unroll
    for (int c = 0; c < CCH; c++) o[c] = acc[c];
}

// ---------------------------------------------------------------------------
// Launch
// ---------------------------------------------------------------------------
extern "C" void kernel_launch(void* const* d_in, const int* in_sizes, int n_in,
                              void* d_out, int out_size) {
    (void)in_sizes; (void)n_in; (void)out_size;
    const float* integ = (const float*)d_in[0];   // [B,K,N,N] f32
    const float* x2    = (const float*)d_in[1];   // [B,C,N*N] f32
    const int*   mask  = (const int*)d_in[2];     // [B,N,N]   i32
    const float* conv  = (const float*)d_in[3];   // [K]       f32
    float* out = (float*)d_out;                   // [B,N*N,C] f32

    const int total4 = BB * KCH * NN / 4;         // 1,073,152 = 1048*1024
    k_pre<<<total4 / 1024, 256>>>((const float4*)integ, (const int4*)mask);

    dim3 gw(NSIDE / TJ, NSIDE / TI, BB);          // 16 x 16 x 2 = 512 blocks
    k_weights<<<gw, 128>>>(mask, conv);

    dim3 gg(NSIDE / 16, NSIDE / 16, BB);
    k_gather<<<gg, 256>>>(x2, out);
}

// round 17
// speedup vs baseline: 1.2091x; 1.0035x over previous
#include <cuda_runtime.h>
#include <cstdint>

typedef unsigned long long ull;

// Problem constants (fixed by the dataset)
#define RWIN   3
#define NW     49          // (2R+1)^2
#define NSIDE  128
#define NN     (NSIDE*NSIDE)
#define KCH    131
#define CCH    21
#define BB     2

// Scratch (device globals; no allocation allowed)
// (t,u) = (exp(xm), exp(-xm)) pairs; float4 = 2 pairs, 16B-aligned IO.
__device__ float4 g_TU[(size_t)BB * KCH * NN / 2];
// g_A[w][b][pix] : per-window-tap mixing weights (49 planes, coalesced)
__device__ float  g_A[(size_t)NW * BB * NN];

// ---------------------------------------------------------------------------
// Kernel P: precompute (exp(xm), exp(-xm)). 2 float4 per thread (MLP=4).
// (R11-measured fastest variant: 12.9us.)
// ---------------------------------------------------------------------------
__global__ __launch_bounds__(256) void k_pre(const float4* __restrict__ x,
                                             const int4* __restrict__ mask) {
    const int total4 = BB * KCH * NN / 4;
    int i0 = blockIdx.x * 512 + threadIdx.x;
    int i1 = i0 + 256;
    bool ok0 = i0 < total4, ok1 = i1 < total4;
    float4 v0, v1; int4 m0, m1;
    if (ok0) { v0 = x[i0]; m0 = mask[(i0 / (KCH * NN / 4)) * (NN / 4) + (i0 & (NN / 4 - 1))]; }
    if (ok1) { v1 = x[i1]; m1 = mask[(i1 / (KCH * NN / 4)) * (NN / 4) + (i1 & (NN / 4 - 1))]; }
    if (ok0) {
        float a = m0.x ? v0.x : 0.f, b = m0.y ? v0.y : 0.f;
        float c = m0.z ? v0.z : 0.f, d = m0.w ? v0.w : 0.f;
        g_TU[2 * (size_t)i0]     = make_float4(__expf(a), __expf(-a), __expf(b), __expf(-b));
        g_TU[2 * (size_t)i0 + 1] = make_float4(__expf(c), __expf(-c), __expf(d), __expf(-d));
    }
    if (ok1) {
        float a = m1.x ? v1.x : 0.f, b = m1.y ? v1.y : 0.f;
        float c = m1.z ? v1.z : 0.f, d = m1.w ? v1.w : 0.f;
        g_TU[2 * (size_t)i1]     = make_float4(__expf(a), __expf(-a), __expf(b), __expf(-b));
        g_TU[2 * (size_t)i1 + 1] = make_float4(__expf(c), __expf(-c), __expf(d), __expf(-d));
    }
}

// ---------------------------------------------------------------------------
// Kernel W: per-pixel window weights A[w].
//   e_w = max(u_c*t_b, t_c*u_b) = exp(|xm_c - xm_b|)   (0 for OOB since TU=0)
//   A[w] = sum_k conv[k] * e_w / sum_w e_w              (selected pixels only)
//
// 8x8 pixel tile, 128 threads = 2 threads/pixel split by window ROW:
//   half0 -> dy in [0,3] (28 taps), half1 -> dy in [4,6] (21 taps).
// TWO channels per pipeline stage (66 stages), 3 buffers, prefetch dist 2.
// ONE barrier per stage (top-of-loop barrier alone is sufficient: the buffer
// loaded at stage kp is (kp+2)%3, which is exactly the buffer all warps
// finished reading at stage kp-1 -- before they could pass this barrier).
// __launch_bounds__(128,4): 592 block-slots >= 512 blocks -> SINGLE WAVE
// (the old occ=3 config left a 68-block, 1-block/SM latency-exposed tail).
// ---------------------------------------------------------------------------
#define TI  8
#define TJ  8
#define HWD 14      // halo tile = (TI+6) x (TJ+6)
#define STW 26      // smem row stride in 8-byte words

#define NPAIR ((KCH + 1) / 2)   // 66

__global__ __launch_bounds__(128, 4) void k_weights(const int* __restrict__ mask,
                                                    const float* __restrict__ conv) {
    __shared__ __align__(16) ull tu[3][2][HWD * STW];   // 3 stages x 2 channels

    const int tid  = threadIdx.x;
    const int b    = blockIdx.z;
    const int ti0  = blockIdx.y * TI, tj0 = blockIdx.x * TJ;
    const int px   = tid >> 1, half = tid & 1;
    const int pi   = px >> 3, pj = px & 7;
    const int pix  = (ti0 + pi) * NSIDE + tj0 + pj;
    const int msk  = mask[b * NN + pix];
    const int base = (pi + 4 * half) * STW + pj;     // first tap row for my dy range
    const int cbase = (pi + 3) * STW + (pj + 3);     // center (dy=3,dx=3)

    // --- one channel's 14x14 float2 tile via cp.async (no commit) ---
    auto load_ch = [&](int k, ull* dsts) {
        const float2* gsrc = (const float2*)g_TU + (size_t)(b * KCH + k) * NN;
        unsigned sdst = (unsigned)__cvta_generic_to_shared(dsts);
#pragma unroll
        for (int e0 = 0; e0 < 2; e0++) {
            int e = tid + e0 * 128;
            if (e < HWD * HWD) {
                int r = e / HWD, c = e - r * HWD;
                int gi2 = ti0 - 3 + r, gj2 = tj0 - 3 + c;
                bool ok = ((unsigned)gi2 < NSIDE) && ((unsigned)gj2 < NSIDE);
                int gic = min(max(gi2, 0), NSIDE - 1);
                int gjc = min(max(gj2, 0), NSIDE - 1);
                const void* src = (const void*)(gsrc + gic * NSIDE + gjc);
                unsigned dst = sdst + (unsigned)((r * STW + c) * 8);
                int sz = ok ? 8 : 0;   // src-size 0 -> zero fill (kills OOB taps)
                asm volatile("cp.async.ca.shared.global [%0], [%1], 8, %2;\n"
                             :: "r"(dst), "l"(src), "r"(sz));
            }
        }
    };
    auto load_pair = [&](int kp, int buf) {
        int k0 = 2 * kp;
        load_ch(k0, tu[buf][0]);
        if (k0 + 1 < KCH) load_ch(k0 + 1, tu[buf][1]);
        asm volatile("cp.async.commit_group;\n");
    };

    float acc[28];
#pragma unroll
    for (int t = 0; t < 28; t++) acc[t] = 0.0f;

    // --- per-channel compute (tree-style S reduction) ---
    auto compute = [&](const ull* __restrict__ T, float cv) {
        ull c64 = T[cbase];                       // (t_c, u_c)
        unsigned clo, chi;
        asm("mov.b64 {%0,%1}, %2;" : "=r"(clo), "=r"(chi) : "l"(c64));
        ull Cw;                                   // (u_c, t_c)
        asm("mov.b64 %0, {%1,%2};" : "=l"(Cw) : "r"(chi), "r"(clo));

        float e[28];
        float s0 = 0.f, s1 = 0.f, s2 = 0.f, s3 = 0.f;
#pragma unroll
        for (int r = 0; r < 4; r++) {
            if (r < 3 || half == 0) {             // half1 has only 3 rows
#pragma unroll
                for (int dx = 0; dx < 7; dx++) {
                    ull p = T[base + r * STW + dx];     // (t_b, u_b)
                    ull mr;
                    asm("mul.rn.f32x2 %0, %1, %2;" : "=l"(mr) : "l"(Cw), "l"(p));
                    unsigned ra, rb;
                    asm("mov.b64 {%0,%1}, %2;" : "=r"(ra), "=r"(rb) : "l"(mr));
                    float ev = fmaxf(__uint_as_float(ra), __uint_as_float(rb));
                    const int t = r * 7 + dx;
                    e[t] = ev;
                    if      ((t & 3) == 0) s0 += ev;
                    else if ((t & 3) == 1) s1 += ev;
                    else if ((t & 3) == 2) s2 += ev;
                    else                   s3 += ev;
                }
            }
        }
        float s = (s0 + s1) + (s2 + s3);
        // pair lanes (2p, 2p+1) share the pixel -> same msk -> both present
        float stot = s + __shfl_xor_sync(__activemask(), s, 1);
        float coeff = __fdividef(cv, stot);
#pragma unroll
        for (int t = 0; t < 28; t++)
            if (t < 28 - 7 * half)
                acc[t] = fmaf(coeff, e[t], acc[t]);
    };

    load_pair(0, 0);
    load_pair(1, 1);

    for (int kp = 0; kp < NPAIR; kp++) {
        asm volatile("cp.async.wait_group 1;\n");
        __syncthreads();
        if (kp + 2 < NPAIR) load_pair(kp + 2, (kp + 2) % 3);

        if (msk) {
            const int k0 = 2 * kp;
            float cv0 = __ldg(conv + k0);
            compute(tu[kp % 3][0], cv0);
            if (k0 + 1 < KCH) {
                float cv1 = __ldg(conv + k0 + 1);
                compute(tu[kp % 3][1], cv1);
            }
        }
    }

    // writeout: half0 -> w 0..27, half1 -> w 28..48; unselected rows = 0
    const int wb = half ? 28 : 0;
#pragma unroll
    for (int t = 0; t < 28; t++)
        if (t < 28 - 7 * half)
            g_A[((size_t)(wb + t) * BB + b) * NN + pix] = msk ? acc[t] : 0.0f;
}

// ---------------------------------------------------------------------------
// Kernel G: output gather (1 px/thread).
//   y[b, q=(i,j), c] = sum_{du,dv in [-3,3]} A[w=(3-du)*7+(3-dv)][p=(i+du,j+dv)]
//                      * x2[b, c, p]
// ---------------------------------------------------------------------------
__global__ __launch_bounds__(256) void k_gather(const float* __restrict__ x2,
                                                float* __restrict__ out) {
    const int b  = blockIdx.z;
    const int tid = threadIdx.x;
    const int i2 = blockIdx.y * 16 + (tid >> 4);
    const int j2 = blockIdx.x * 16 + (tid & 15);

    float acc[CCH];
#pragma unroll
    for (int c = 0; c < CCH; c++) acc[c] = 0.0f;

    const float* x2b = x2 + (size_t)b * CCH * NN;

#pragma unroll 1
    for (int du = -3; du <= 3; du++) {
        const int pi = i2 + du;
        if ((unsigned)pi >= NSIDE) continue;
#pragma unroll 1
        for (int dv = -3; dv <= 3; dv++) {
            const int pj = j2 + dv;
            if ((unsigned)pj >= NSIDE) continue;
            const int w = (3 - du) * 7 + (3 - dv);
            const int p = pi * NSIDE + pj;
            const float a = g_A[((size_t)w * BB + b) * NN + p];
            const float* f = x2b + p;
#pragma unroll
            for (int c = 0; c < CCH; c++)
                acc[c] = fmaf(a, f[(size_t)c * NN], acc[c]);
        }
    }

    float* o = out + ((size_t)b * NN + i2 * NSIDE + j2) * CCH;
#pragma unroll
    for (int c = 0; c < CCH; c++) o[c] = acc[c];
}

// ---------------------------------------------------------------------------
// Launch
// ---------------------------------------------------------------------------
extern "C" void kernel_launch(void* const* d_in, const int* in_sizes, int n_in,
                              void* d_out, int out_size) {
    (void)in_sizes; (void)n_in; (void)out_size;
    const float* integ = (const float*)d_in[0];   // [B,K,N,N] f32
    const float* x2    = (const float*)d_in[1];   // [B,C,N*N] f32
    const int*   mask  = (const int*)d_in[2];     // [B,N,N]   i32
    const float* conv  = (const float*)d_in[3];   // [K]       f32
    float* out = (float*)d_out;                   // [B,N*N,C] f32

    const int total4 = BB * KCH * NN / 4;
    k_pre<<<(total4 + 511) / 512, 256>>>((const float4*)integ, (const int4*)mask);

    dim3 gw(NSIDE / TJ, NSIDE / TI, BB);          // 16 x 16 x 2 = 512 blocks
    k_weights<<<gw, 128>>>(mask, conv);

    dim3 gg(NSIDE / 16, NSIDE / 16, BB);
    k_gather<<<gg, 256>>>(x2, out);
}